// round 14
// baseline (speedup 1.0000x reference)
#include <cuda_runtime.h>
#include <cuda_bf16.h>
#include <math_constants.h>
#include <cstdint>

#define GN 50000
#define GE 800000
#define GET (GE + GN)   // edges incl. self loops
#define NSCAN_BLK 49    // ceil(GN/1024)

// ---------------- scratch (device globals; no allocs allowed) ----------------
__device__ __align__(16) float g_xl1[GN * 256];     // x @ W_l1
__device__ __align__(16) float g_xr1[GN * 256];     // x @ W_r1
__device__ __align__(16) float g_hl2[GN * 10];
__device__ __align__(16) float g_hr2[GN * 10];
// K-concat 3-split operands: A' = [hi | hi | lo] (K=768), B' = [hi | lo | hi]
__device__ __align__(16) __nv_bfloat16 g_xs[(size_t)GN * 768];
__device__ __align__(16) __nv_bfloat16 g_ws[512 * 768];   // rows 0-255: Wl cols, 256-511: Wr cols
__device__ int g_cnt[GN];
__device__ int g_rowptr[GN + 1];
__device__ int g_cursor[GN];
__device__ int g_csr_src[GET];
__device__ int g_bsum[NSCAN_BLK];
__device__ int g_boff[NSCAN_BLK];
// degree-sorted node order (load balancing for layer1/layer2)
__device__ int g_dcnt[256];
__device__ int g_doff[256];
__device__ int g_dcur[256];
__device__ int g_order[GN];

__device__ __forceinline__ float lrelu(float v) { return v > 0.0f ? v : 0.2f * v; }

__device__ __forceinline__ uint32_t smem_u32(const void* p) {
    uint32_t a;
    asm("{ .reg .u64 t; cvta.to.shared.u64 t, %1; cvt.u32.u64 %0, t; }" : "=r"(a) : "l"(p));
    return a;
}

#define CPA16(dst, src) \
    asm volatile("cp.async.cg.shared.global [%0], [%1], 16;" :: "r"(dst), "l"(src))
#define CPA_COMMIT() asm volatile("cp.async.commit_group;")

__device__ __forceinline__ void ldsm_x4(uint32_t& r0, uint32_t& r1, uint32_t& r2, uint32_t& r3,
                                        uint32_t addr) {
    asm volatile("ldmatrix.sync.aligned.m8n8.x4.shared.b16 {%0,%1,%2,%3}, [%4];"
                 : "=r"(r0), "=r"(r1), "=r"(r2), "=r"(r3) : "r"(addr));
}

__device__ __forceinline__ void mma16816(float* c, const uint32_t* a, const uint32_t* b) {
    asm volatile(
        "mma.sync.aligned.m16n8k16.row.col.f32.bf16.bf16.f32 "
        "{%0,%1,%2,%3}, {%4,%5,%6,%7}, {%8,%9}, {%0,%1,%2,%3};"
        : "+f"(c[0]), "+f"(c[1]), "+f"(c[2]), "+f"(c[3])
        : "r"(a[0]), "r"(a[1]), "r"(a[2]), "r"(a[3]), "r"(b[0]), "r"(b[1]));
}

__device__ __forceinline__ uint32_t sw128(uint32_t off) {
    return off ^ ((off >> 3) & 0x70);
}

// ---------------- init: zero histograms ----------------
__global__ void zero_cnt_kernel() {
    int i = blockIdx.x * blockDim.x + threadIdx.x;
    if (i < GN) g_cnt[i] = 0;
    if (i < 256) { g_dcnt[i] = 0; g_dcur[i] = 0; }
}

// ---------------- CSR build ----------------
__global__ void hist_kernel(const int* __restrict__ ei) {
    int e = blockIdx.x * blockDim.x + threadIdx.x;
    if (e >= GET) return;
    int dst = (e < GE) ? ei[GE + e] : (e - GE);
    atomicAdd(&g_cnt[dst], 1);
}

__global__ void scan1_kernel() {
    __shared__ int warp_tot[32];
    int tid = threadIdx.x;
    int i = blockIdx.x * 1024 + tid;
    int lane = tid & 31, wid = tid >> 5;
    int v = (i < GN) ? g_cnt[i] : 0;
    int s = v;
#pragma unroll
    for (int off = 1; off < 32; off <<= 1) {
        int t = __shfl_up_sync(0xffffffffu, s, off);
        if (lane >= off) s += t;
    }
    if (lane == 31) warp_tot[wid] = s;
    __syncthreads();
    if (wid == 0) {
        int w = warp_tot[lane];
        int ws = w;
#pragma unroll
        for (int off = 1; off < 32; off <<= 1) {
            int t = __shfl_up_sync(0xffffffffu, ws, off);
            if (lane >= off) ws += t;
        }
        warp_tot[lane] = ws - w;
        if (lane == 31) g_bsum[blockIdx.x] = ws;
    }
    __syncthreads();
    int excl = s - v + warp_tot[wid];
    if (i < GN) g_rowptr[i] = excl;
}

__global__ void scan2_kernel() {
    int tid = threadIdx.x;
    __shared__ int sh[64];
    int v = (tid < NSCAN_BLK) ? g_bsum[tid] : 0;
    sh[tid] = v;
    __syncthreads();
    if (tid == 0) {
        int run = 0;
        for (int b = 0; b < NSCAN_BLK; b++) { g_boff[b] = run; run += sh[b]; }
        g_rowptr[GN] = GET;
    }
}

__global__ void scan3_kernel() {
    int i = blockIdx.x * 1024 + threadIdx.x;
    if (i >= GN) return;
    int r = g_rowptr[i] + g_boff[blockIdx.x];
    g_rowptr[i] = r;
    g_cursor[i] = r;
}

__global__ void scatter_kernel(const int* __restrict__ ei) {
    int e = blockIdx.x * blockDim.x + threadIdx.x;
    if (e >= GET) return;
    int src, dst;
    if (e < GE) { src = ei[e]; dst = ei[GE + e]; }
    else        { src = dst = e - GE; }
    int pos = atomicAdd(&g_cursor[dst], 1);
    g_csr_src[pos] = src;
}

// ---------------- degree-sort (descending) for load-balanced node order ----------------
__global__ void deg_hist_kernel() {
    int i = blockIdx.x * blockDim.x + threadIdx.x;
    if (i >= GN) return;
    int d = g_cnt[i]; if (d > 255) d = 255;
    atomicAdd(&g_dcnt[d], 1);
}

__global__ void deg_scan_kernel() {
    __shared__ int sh[256];
    int t = threadIdx.x;
    sh[t] = g_dcnt[t];
    __syncthreads();
    if (t == 0) {
        int run = 0;
        for (int d = 255; d >= 0; d--) { g_doff[d] = run; run += sh[d]; }  // descending
    }
}

__global__ void deg_scatter_kernel() {
    int i = blockIdx.x * blockDim.x + threadIdx.x;
    if (i >= GN) return;
    int d = g_cnt[i]; if (d > 255) d = 255;
    int pos = g_doff[d] + atomicAdd(&g_dcur[d], 1);
    g_order[pos] = i;
}

// ---------------- bf16 K-concat split conversions ----------------
__global__ void convert_x_kernel(const float* __restrict__ x) {
    int i = blockIdx.x * blockDim.x + threadIdx.x;   // over GN*64 float4s
    if (i >= GN * 64) return;
    int row = i >> 6, k4 = (i & 63) * 4;
    float4 v = reinterpret_cast<const float4*>(x)[i];
    __nv_bfloat16 h0 = __float2bfloat16(v.x), h1 = __float2bfloat16(v.y);
    __nv_bfloat16 h2 = __float2bfloat16(v.z), h3 = __float2bfloat16(v.w);
    __nv_bfloat16 l0 = __float2bfloat16(v.x - __bfloat162float(h0));
    __nv_bfloat16 l1 = __float2bfloat16(v.y - __bfloat162float(h1));
    __nv_bfloat16 l2 = __float2bfloat16(v.z - __bfloat162float(h2));
    __nv_bfloat16 l3 = __float2bfloat16(v.w - __bfloat162float(h3));
    __nv_bfloat162 hA(h0, h1), hB(h2, h3), lA(l0, l1), lB(l2, l3);
    size_t base = (size_t)row * 768 + k4;
    __nv_bfloat162* p0 = reinterpret_cast<__nv_bfloat162*>(&g_xs[base]);
    __nv_bfloat162* p1 = reinterpret_cast<__nv_bfloat162*>(&g_xs[base + 256]);
    __nv_bfloat162* p2 = reinterpret_cast<__nv_bfloat162*>(&g_xs[base + 512]);
    p0[0] = hA; p0[1] = hB;
    p1[0] = hA; p1[1] = hB;
    p2[0] = lA; p2[1] = lB;
}

__global__ void convert_w_kernel(const float* __restrict__ Wl1, const float* __restrict__ Wr1) {
    int i = blockIdx.x * blockDim.x + threadIdx.x;   // 512*256
    if (i >= 512 * 256) return;
    int n = i >> 8, k = i & 255;
    float w = (n < 256) ? Wl1[k * 256 + n] : Wr1[k * 256 + (n - 256)];
    __nv_bfloat16 h = __float2bfloat16(w);
    __nv_bfloat16 l = __float2bfloat16(w - __bfloat162float(h));
    size_t base = (size_t)n * 768;
    g_ws[base + k] = h;
    g_ws[base + 256 + k] = l;
    g_ws[base + 512 + k] = h;
}

// ---------------- GEMM1 via mma.sync bf16 (M=50000, N=512, K=768) ----------------
// CTA tile 128x64, BK=64, 8 warps (4M x 2N), warp tile 32x32,
// cp.async double buffer, ldmatrix.x4 fragment loads.
// grid = (8 nb, 391 rb): same-rb CTAs adjacent in bid order -> A tile L2 reuse.
#define GBM 128
#define GBN 64
#define GBK 64
#define A_STAGE (GBM * GBK * 2)           // 16384
#define B_STAGE (GBN * GBK * 2)           // 8192
#define STAGE_BYTES (A_STAGE + B_STAGE)   // 24576
#define KITERS 12                          // 768/64

__global__ void __launch_bounds__(256, 2) gemm1_mma_kernel() {
    __shared__ __align__(128) char smem[2 * STAGE_BYTES];
    uint32_t sb = smem_u32(smem);
    int tid = threadIdx.x;
    int wid = tid >> 5, lane = tid & 31;
    int nb = blockIdx.x, rb = blockIdx.y;   // nb fastest -> A-tile L2 reuse
    int row0 = rb * GBM;
    int g = lane >> 2, t2 = (lane & 3) * 2;
    int warpM = wid & 3, warpN = wid >> 2;
    int lj = lane >> 3, lr = lane & 7;    // ldmatrix: matrix id, row-in-matrix

    const char* Ab = (const char*)g_xs;
    const char* Bb = (const char*)g_ws;

    float c[2][4][4];
#pragma unroll
    for (int mt = 0; mt < 2; mt++)
#pragma unroll
        for (int nt = 0; nt < 4; nt++)
#pragma unroll
            for (int q = 0; q < 4; q++) c[mt][nt][q] = 0.0f;

    auto issue = [&](int kt, int buf) {
        uint32_t sA = sb + buf * STAGE_BYTES;
        uint32_t sB = sA + A_STAGE;
        int kc = kt * GBK;
#pragma unroll
        for (int q = 0; q < 4; q++) {
            int id = tid + q * 256;
            int m = id >> 3, ch = id & 7;
            int grow = row0 + m; if (grow >= GN) grow = 0;
            const char* src = Ab + (size_t)grow * 1536 + kc * 2 + ch * 16;
            CPA16(sA + sw128(m * 128 + ch * 16), src);
        }
#pragma unroll
        for (int q = 0; q < 2; q++) {
            int id = tid + q * 256;
            int n = id >> 3, ch = id & 7;
            const char* src = Bb + (size_t)(nb * 64 + n) * 1536 + kc * 2 + ch * 16;
            CPA16(sB + sw128(n * 128 + ch * 16), src);
        }
        CPA_COMMIT();
    };

    issue(0, 0);
    for (int t = 0; t < KITERS; t++) {
        if (t + 1 < KITERS) {
            issue(t + 1, (t + 1) & 1);
            asm volatile("cp.async.wait_group 1;");
        } else {
            asm volatile("cp.async.wait_group 0;");
        }
        __syncthreads();
        uint32_t sA = sb + (t & 1) * STAGE_BYTES;
        uint32_t sB = sA + A_STAGE;
#pragma unroll
        for (int ks = 0; ks < 4; ks++) {
            int kb = ks * 16;
            uint32_t a[2][4], b[4][2];
#pragma unroll
            for (int mt = 0; mt < 2; mt++) {
                int m0 = warpM * 32 + mt * 16;
                uint32_t off = (uint32_t)(m0 + (lj & 1) * 8 + lr) * 128
                             + (uint32_t)(kb + (lj >> 1) * 8) * 2;
                ldsm_x4(a[mt][0], a[mt][1], a[mt][2], a[mt][3], sA + sw128(off));
            }
#pragma unroll
            for (int np = 0; np < 2; np++) {
                int ntj = np * 2 + (lj >> 1);
                uint32_t off = (uint32_t)(warpN * 32 + ntj * 8 + lr) * 128
                             + (uint32_t)(kb + (lj & 1) * 8) * 2;
                ldsm_x4(b[np * 2][0], b[np * 2][1], b[np * 2 + 1][0], b[np * 2 + 1][1],
                        sB + sw128(off));
            }
#pragma unroll
            for (int mt = 0; mt < 2; mt++)
#pragma unroll
                for (int nt = 0; nt < 4; nt++)
                    mma16816(c[mt][nt], a[mt], b[nt]);
        }
        __syncthreads();
    }

    float* C = (nb < 4) ? g_xl1 : g_xr1;
    int colBase = (nb & 3) * 64 + warpN * 32;
#pragma unroll
    for (int mt = 0; mt < 2; mt++) {
        int r0 = row0 + warpM * 32 + mt * 16 + g;
#pragma unroll
        for (int nt = 0; nt < 4; nt++) {
            int cc = colBase + nt * 8 + t2;
            if (r0 < GN)
                *reinterpret_cast<float2*>(C + (size_t)r0 * 256 + cc) =
                    make_float2(c[mt][nt][0], c[mt][nt][1]);
            if (r0 + 8 < GN)
                *reinterpret_cast<float2*>(C + (size_t)(r0 + 8) * 256 + cc) =
                    make_float2(c[mt][nt][2], c[mt][nt][3]);
        }
    }
}

// ---------------- layer1 fused: softmax-aggregate + bias/relu + (h @ W2) ----------------
__device__ __forceinline__ float score8(const float4& xl0, const float4& xl1,
                                        const float4& xr0, const float4& xr1,
                                        const float4& at0, const float4& at1) {
    float t = lrelu(xl0.x + xr0.x) * at0.x + lrelu(xl0.y + xr0.y) * at0.y
            + lrelu(xl0.z + xr0.z) * at0.z + lrelu(xl0.w + xr0.w) * at0.w
            + lrelu(xl1.x + xr1.x) * at1.x + lrelu(xl1.y + xr1.y) * at1.y
            + lrelu(xl1.z + xr1.z) * at1.z + lrelu(xl1.w + xr1.w) * at1.w;
    return t;
}

#define SOFTMAX_STEP(T, V0, V1) do { \
    float mn = fmaxf(m, (T)); \
    float f = __expf(m - mn); \
    float e = __expf((T) - mn); \
    d = d * f + e; \
    acc0.x = acc0.x * f + e * (V0).x; acc0.y = acc0.y * f + e * (V0).y; \
    acc0.z = acc0.z * f + e * (V0).z; acc0.w = acc0.w * f + e * (V0).w; \
    acc1.x = acc1.x * f + e * (V1).x; acc1.y = acc1.y * f + e * (V1).y; \
    acc1.z = acc1.z * f + e * (V1).z; acc1.w = acc1.w * f + e * (V1).w; \
    m = mn; \
} while (0)

__global__ void layer1_fused_kernel(const float* __restrict__ att1,
                                    const float* __restrict__ b1,
                                    const float* __restrict__ Wl2,
                                    const float* __restrict__ Wr2) {
    // sW[q][lane][jj] (jj padded to 21): W2cat[lane*8+q][jj], conflict-free reads
    __shared__ float sW[8 * 32 * 21];
    int tid = threadIdx.x;
    for (int i = tid; i < 8 * 32 * 20; i += 256) {
        int jj = i % 20;
        int cidx = i / 20;            // 0..255 channel
        int q = cidx & 7, ls = cidx >> 3;
        float w = (jj < 10) ? Wl2[cidx * 10 + jj] : Wr2[cidx * 10 + (jj - 10)];
        sW[q * (32 * 21) + ls * 21 + jj] = w;
    }
    __syncthreads();

    int gt = blockIdx.x * blockDim.x + tid;
    int nidx = gt >> 5;
    int lane = tid & 31;
    if (nidx >= GN) return;
    int node = g_order[nidx];    // degree-sorted order: warps in a block have similar work

    const float4* xr4 = reinterpret_cast<const float4*>(g_xr1) + (size_t)node * 64;
    float4 xr0 = xr4[lane * 2];
    float4 xr1 = xr4[lane * 2 + 1];
    float4 at0 = reinterpret_cast<const float4*>(att1)[lane * 2];
    float4 at1 = reinterpret_cast<const float4*>(att1)[lane * 2 + 1];

    float4 acc0 = make_float4(0.f, 0.f, 0.f, 0.f);
    float4 acc1 = make_float4(0.f, 0.f, 0.f, 0.f);
    float m = -CUDART_INF_F, d = 0.0f;

    int beg = g_rowptr[node], end = g_rowptr[node + 1];
    int j = beg;
    for (; j + 2 <= end; j += 2) {
        int s0 = g_csr_src[j];
        int s1 = g_csr_src[j + 1];
        const float4* p0 = reinterpret_cast<const float4*>(g_xl1) + (size_t)s0 * 64 + lane * 2;
        const float4* p1 = reinterpret_cast<const float4*>(g_xl1) + (size_t)s1 * 64 + lane * 2;
        float4 a0 = __ldg(p0);
        float4 a1 = __ldg(p0 + 1);
        float4 c0 = __ldg(p1);
        float4 c1 = __ldg(p1 + 1);

        float t0 = score8(a0, a1, xr0, xr1, at0, at1);
        float t1 = score8(c0, c1, xr0, xr1, at0, at1);
        t0 += __shfl_xor_sync(0xffffffffu, t0, 4);
        t1 += __shfl_xor_sync(0xffffffffu, t1, 4);
        t0 += __shfl_xor_sync(0xffffffffu, t0, 2);
        t1 += __shfl_xor_sync(0xffffffffu, t1, 2);
        t0 += __shfl_xor_sync(0xffffffffu, t0, 1);
        t1 += __shfl_xor_sync(0xffffffffu, t1, 1);

        SOFTMAX_STEP(t0, a0, a1);
        SOFTMAX_STEP(t1, c0, c1);
    }
    if (j < end) {
        int s0 = g_csr_src[j];
        const float4* p0 = reinterpret_cast<const float4*>(g_xl1) + (size_t)s0 * 64 + lane * 2;
        float4 a0 = __ldg(p0);
        float4 a1 = __ldg(p0 + 1);
        float t0 = score8(a0, a1, xr0, xr1, at0, at1);
        t0 += __shfl_xor_sync(0xffffffffu, t0, 4);
        t0 += __shfl_xor_sync(0xffffffffu, t0, 2);
        t0 += __shfl_xor_sync(0xffffffffu, t0, 1);
        SOFTMAX_STEP(t0, a0, a1);
    }

    float inv = 1.0f / d;
    float4 bb0 = reinterpret_cast<const float4*>(b1)[lane * 2];
    float4 bb1 = reinterpret_cast<const float4*>(b1)[lane * 2 + 1];
    float hv[8];
    hv[0] = fmaxf(acc0.x * inv + bb0.x, 0.f); hv[1] = fmaxf(acc0.y * inv + bb0.y, 0.f);
    hv[2] = fmaxf(acc0.z * inv + bb0.z, 0.f); hv[3] = fmaxf(acc0.w * inv + bb0.w, 0.f);
    hv[4] = fmaxf(acc1.x * inv + bb1.x, 0.f); hv[5] = fmaxf(acc1.y * inv + bb1.y, 0.f);
    hv[6] = fmaxf(acc1.z * inv + bb1.z, 0.f); hv[7] = fmaxf(acc1.w * inv + bb1.w, 0.f);

    // fused h @ [Wl2 | Wr2]: 20 outputs per node
    const float* sWl = &sW[lane * 21];
    float myval = 0.0f;
#pragma unroll
    for (int jj = 0; jj < 20; jj++) {
        float s = 0.0f;
#pragma unroll
        for (int q = 0; q < 8; q++)
            s += hv[q] * sWl[q * (32 * 21) + jj];
        s += __shfl_xor_sync(0xffffffffu, s, 16);
        s += __shfl_xor_sync(0xffffffffu, s, 8);
        s += __shfl_xor_sync(0xffffffffu, s, 4);
        s += __shfl_xor_sync(0xffffffffu, s, 2);
        s += __shfl_xor_sync(0xffffffffu, s, 1);
        if (lane == jj) myval = s;
    }
    if (lane < 10)       g_hl2[node * 10 + lane] = myval;
    else if (lane < 20)  g_hr2[node * 10 + lane - 10] = myval;
}

// ---------------- layer2 fused ----------------
__global__ void layer2_fused_kernel(const float* __restrict__ att2,
                                    const float* __restrict__ b2,
                                    float* __restrict__ out) {
    int gt = blockIdx.x * blockDim.x + threadIdx.x;
    int nidx = gt >> 5;
    int lane = threadIdx.x & 31;
    if (nidx >= GN) return;
    int node = g_order[nidx];

    float hr = (lane < 10) ? g_hr2[node * 10 + lane] : 0.0f;
    float at = (lane < 10) ? att2[lane] : 0.0f;
    float m = -CUDART_INF_F, d = 0.0f, acc = 0.0f;

    int beg = g_rowptr[node], end = g_rowptr[node + 1];
    for (int j = beg; j < end; j++) {
        int src = g_csr_src[j];
        float hl = (lane < 10) ? __ldg(&g_hl2[src * 10 + lane]) : 0.0f;
        float v = lrelu(hl + hr) * at;
        v += __shfl_xor_sync(0xffffffffu, v, 16);
        v += __shfl_xor_sync(0xffffffffu, v, 8);
        v += __shfl_xor_sync(0xffffffffu, v, 4);
        v += __shfl_xor_sync(0xffffffffu, v, 2);
        v += __shfl_xor_sync(0xffffffffu, v, 1);
        float s = v;
        float mn = fmaxf(m, s);
        float f = __expf(m - mn);
        float e = __expf(s - mn);
        d = d * f + e;
        acc = acc * f + e * hl;
        m = mn;
    }
    if (lane < 10)
        out[node * 10 + lane] = acc / d + b2[lane];
}

// ---------------- launch ----------------
extern "C" void kernel_launch(void* const* d_in, const int* in_sizes, int n_in,
                              void* d_out, int out_size) {
    const float* x    = (const float*)d_in[0];
    const int*   ei   = (const int*)d_in[1];
    const float* Wl1  = (const float*)d_in[2];
    const float* Wr1  = (const float*)d_in[3];
    const float* att1 = (const float*)d_in[4];
    const float* b1   = (const float*)d_in[5];
    const float* Wl2  = (const float*)d_in[6];
    const float* Wr2  = (const float*)d_in[7];
    const float* att2 = (const float*)d_in[8];
    const float* b2   = (const float*)d_in[9];
    float* out = (float*)d_out;

    static cudaStream_t s2 = nullptr;
    static cudaEvent_t ev_fork = nullptr, ev_join = nullptr;
    static int inited = 0;
    if (!inited) {
        cudaStreamCreateWithFlags(&s2, cudaStreamNonBlocking);
        cudaEventCreateWithFlags(&ev_fork, cudaEventDisableTiming);
        cudaEventCreateWithFlags(&ev_join, cudaEventDisableTiming);
        inited = 1;
    }

    // fork: CSR build + degree-sort chain on s2, converts + gemm1 on the main stream.
    // Submission order keeps gemm1 at slot #4 (the profiled slot).
    cudaEventRecord(ev_fork, 0);
    cudaStreamWaitEvent(s2, ev_fork, 0);

    convert_x_kernel<<<(GN * 64 + 255) / 256, 256>>>(x);                 // 1 (main)
    convert_w_kernel<<<(512 * 256 + 255) / 256, 256>>>(Wl1, Wr1);        // 2 (main)
    zero_cnt_kernel<<<(GN + 255) / 256, 256, 0, s2>>>();                 // 3 (s2)

    dim3 g1(8, (GN + GBM - 1) / GBM);                                    // nb fastest
    gemm1_mma_kernel<<<g1, 256>>>();                                     // 4 (main) <-- profiled

    hist_kernel<<<(GET + 255) / 256, 256, 0, s2>>>(ei);                  // s2
    scan1_kernel<<<NSCAN_BLK, 1024, 0, s2>>>();                          // s2
    scan2_kernel<<<1, 64, 0, s2>>>();                                    // s2
    scan3_kernel<<<NSCAN_BLK, 1024, 0, s2>>>();                          // s2
    scatter_kernel<<<(GET + 255) / 256, 256, 0, s2>>>(ei);               // s2
    deg_hist_kernel<<<(GN + 255) / 256, 256, 0, s2>>>();                 // s2
    deg_scan_kernel<<<1, 256, 0, s2>>>();                                // s2
    deg_scatter_kernel<<<(GN + 255) / 256, 256, 0, s2>>>();              // s2
    cudaEventRecord(ev_join, s2);

    // join: layer1 needs both gemm1 (main) and CSR+order (s2)
    cudaStreamWaitEvent(0, ev_join, 0);

    layer1_fused_kernel<<<(GN * 32 + 255) / 256, 256>>>(att1, b1, Wl2, Wr2);
    layer2_fused_kernel<<<(GN * 32 + 255) / 256, 256>>>(att2, b2, out);
}

// round 16
// speedup vs baseline: 1.1058x; 1.1058x over previous
#include <cuda_runtime.h>
#include <cuda_bf16.h>
#include <math_constants.h>
#include <cstdint>

#define GN 50000
#define GE 800000
#define GET (GE + GN)   // edges incl. self loops
#define NSCAN_BLK 49    // ceil(GN/1024)

// ---------------- scratch (device globals; no allocs allowed) ----------------
__device__ __align__(16) float g_xl1[GN * 256];     // x @ W_l1
__device__ __align__(16) float g_xr1[GN * 256];     // x @ W_r1
__device__ __align__(16) float g_hl2[GN * 10];
__device__ __align__(16) float g_hr2[GN * 10];
// K-concat 3-split operands: A' = [hi | hi | lo] (K=768), B' = [hi | lo | hi]
__device__ __align__(16) __nv_bfloat16 g_xs[(size_t)GN * 768];
__device__ __align__(16) __nv_bfloat16 g_ws[512 * 768];   // rows 0-255: Wl cols, 256-511: Wr cols
__device__ int g_cnt[GN];
__device__ int g_rowptr[GN + 1];
__device__ int g_cursor[GN];
__device__ int g_csr_src[GET];
__device__ int g_bsum[NSCAN_BLK];
__device__ int g_boff[NSCAN_BLK];

__device__ __forceinline__ float lrelu(float v) { return v > 0.0f ? v : 0.2f * v; }

__device__ __forceinline__ uint32_t smem_u32(const void* p) {
    uint32_t a;
    asm("{ .reg .u64 t; cvta.to.shared.u64 t, %1; cvt.u32.u64 %0, t; }" : "=r"(a) : "l"(p));
    return a;
}

#define CPA16(dst, src) \
    asm volatile("cp.async.cg.shared.global [%0], [%1], 16;" :: "r"(dst), "l"(src))
#define CPA_COMMIT() asm volatile("cp.async.commit_group;")

__device__ __forceinline__ void ldsm_x4(uint32_t& r0, uint32_t& r1, uint32_t& r2, uint32_t& r3,
                                        uint32_t addr) {
    asm volatile("ldmatrix.sync.aligned.m8n8.x4.shared.b16 {%0,%1,%2,%3}, [%4];"
                 : "=r"(r0), "=r"(r1), "=r"(r2), "=r"(r3) : "r"(addr));
}

__device__ __forceinline__ void mma16816(float* c, const uint32_t* a, const uint32_t* b) {
    asm volatile(
        "mma.sync.aligned.m16n8k16.row.col.f32.bf16.bf16.f32 "
        "{%0,%1,%2,%3}, {%4,%5,%6,%7}, {%8,%9}, {%0,%1,%2,%3};"
        : "+f"(c[0]), "+f"(c[1]), "+f"(c[2]), "+f"(c[3])
        : "r"(a[0]), "r"(a[1]), "r"(a[2]), "r"(a[3]), "r"(b[0]), "r"(b[1]));
}

__device__ __forceinline__ uint32_t sw128(uint32_t off) {
    return off ^ ((off >> 3) & 0x70);
}

// ---------------- init: zero histogram ----------------
__global__ void zero_cnt_kernel() {
    int i = blockIdx.x * blockDim.x + threadIdx.x;
    if (i < GN) g_cnt[i] = 0;
}

// ---------------- CSR build ----------------
__global__ void hist_kernel(const int* __restrict__ ei) {
    int e = blockIdx.x * blockDim.x + threadIdx.x;
    if (e >= GET) return;
    int dst = (e < GE) ? ei[GE + e] : (e - GE);
    atomicAdd(&g_cnt[dst], 1);
}

__global__ void scan1_kernel() {
    __shared__ int warp_tot[32];
    int tid = threadIdx.x;
    int i = blockIdx.x * 1024 + tid;
    int lane = tid & 31, wid = tid >> 5;
    int v = (i < GN) ? g_cnt[i] : 0;
    int s = v;
#pragma unroll
    for (int off = 1; off < 32; off <<= 1) {
        int t = __shfl_up_sync(0xffffffffu, s, off);
        if (lane >= off) s += t;
    }
    if (lane == 31) warp_tot[wid] = s;
    __syncthreads();
    if (wid == 0) {
        int w = warp_tot[lane];
        int ws = w;
#pragma unroll
        for (int off = 1; off < 32; off <<= 1) {
            int t = __shfl_up_sync(0xffffffffu, ws, off);
            if (lane >= off) ws += t;
        }
        warp_tot[lane] = ws - w;
        if (lane == 31) g_bsum[blockIdx.x] = ws;
    }
    __syncthreads();
    int excl = s - v + warp_tot[wid];
    if (i < GN) g_rowptr[i] = excl;
}

__global__ void scan2_kernel() {
    int tid = threadIdx.x;
    __shared__ int sh[64];
    int v = (tid < NSCAN_BLK) ? g_bsum[tid] : 0;
    sh[tid] = v;
    __syncthreads();
    if (tid == 0) {
        int run = 0;
        for (int b = 0; b < NSCAN_BLK; b++) { g_boff[b] = run; run += sh[b]; }
        g_rowptr[GN] = GET;
    }
}

__global__ void scan3_kernel() {
    int i = blockIdx.x * 1024 + threadIdx.x;
    if (i >= GN) return;
    int r = g_rowptr[i] + g_boff[blockIdx.x];
    g_rowptr[i] = r;
    g_cursor[i] = r;
}

__global__ void scatter_kernel(const int* __restrict__ ei) {
    int e = blockIdx.x * blockDim.x + threadIdx.x;
    if (e >= GET) return;
    int src, dst;
    if (e < GE) { src = ei[e]; dst = ei[GE + e]; }
    else        { src = dst = e - GE; }
    int pos = atomicAdd(&g_cursor[dst], 1);
    g_csr_src[pos] = src;
}

// ---------------- bf16 K-concat split conversions ----------------
__global__ void convert_x_kernel(const float* __restrict__ x) {
    int i = blockIdx.x * blockDim.x + threadIdx.x;   // over GN*64 float4s
    if (i >= GN * 64) return;
    int row = i >> 6, k4 = (i & 63) * 4;
    float4 v = reinterpret_cast<const float4*>(x)[i];
    __nv_bfloat16 h0 = __float2bfloat16(v.x), h1 = __float2bfloat16(v.y);
    __nv_bfloat16 h2 = __float2bfloat16(v.z), h3 = __float2bfloat16(v.w);
    __nv_bfloat16 l0 = __float2bfloat16(v.x - __bfloat162float(h0));
    __nv_bfloat16 l1 = __float2bfloat16(v.y - __bfloat162float(h1));
    __nv_bfloat16 l2 = __float2bfloat16(v.z - __bfloat162float(h2));
    __nv_bfloat16 l3 = __float2bfloat16(v.w - __bfloat162float(h3));
    __nv_bfloat162 hA(h0, h1), hB(h2, h3), lA(l0, l1), lB(l2, l3);
    size_t base = (size_t)row * 768 + k4;
    __nv_bfloat162* p0 = reinterpret_cast<__nv_bfloat162*>(&g_xs[base]);
    __nv_bfloat162* p1 = reinterpret_cast<__nv_bfloat162*>(&g_xs[base + 256]);
    __nv_bfloat162* p2 = reinterpret_cast<__nv_bfloat162*>(&g_xs[base + 512]);
    p0[0] = hA; p0[1] = hB;
    p1[0] = hA; p1[1] = hB;
    p2[0] = lA; p2[1] = lB;
}

__global__ void convert_w_kernel(const float* __restrict__ Wl1, const float* __restrict__ Wr1) {
    int i = blockIdx.x * blockDim.x + threadIdx.x;   // 512*256
    if (i >= 512 * 256) return;
    int n = i >> 8, k = i & 255;
    float w = (n < 256) ? Wl1[k * 256 + n] : Wr1[k * 256 + (n - 256)];
    __nv_bfloat16 h = __float2bfloat16(w);
    __nv_bfloat16 l = __float2bfloat16(w - __bfloat162float(h));
    size_t base = (size_t)n * 768;
    g_ws[base + k] = h;
    g_ws[base + 256 + k] = l;
    g_ws[base + 512 + k] = h;
}

// ---------------- GEMM1 via mma.sync bf16 (M=50000, N=512, K=768) ----------------
// CTA tile 128x64, BK=64, 8 warps (4M x 2N), warp tile 32x32,
// 3-stage cp.async pipeline, ldmatrix.x4 fragment loads.
// grid = (8 nb, 391 rb): same-rb CTAs adjacent in bid order -> A tile L2 reuse.
#define GBM 128
#define GBN 64
#define GBK 64
#define A_STAGE (GBM * GBK * 2)           // 16384
#define B_STAGE (GBN * GBK * 2)           // 8192
#define STAGE_BYTES (A_STAGE + B_STAGE)   // 24576
#define NSTAGE 3
#define GSMEM_BYTES (NSTAGE * STAGE_BYTES) // 73728
#define KITERS 12                          // 768/64

__global__ void __launch_bounds__(256, 2) gemm1_mma_kernel() {
    extern __shared__ __align__(128) char smem[];
    uint32_t sb = smem_u32(smem);
    int tid = threadIdx.x;
    int wid = tid >> 5, lane = tid & 31;
    int nb = blockIdx.x, rb = blockIdx.y;   // nb fastest -> A-tile L2 reuse
    int row0 = rb * GBM;
    int g = lane >> 2, t2 = (lane & 3) * 2;
    int warpM = wid & 3, warpN = wid >> 2;
    int lj = lane >> 3, lr = lane & 7;    // ldmatrix: matrix id, row-in-matrix

    const char* Ab = (const char*)g_xs;
    const char* Bb = (const char*)g_ws;

    float c[2][4][4];
#pragma unroll
    for (int mt = 0; mt < 2; mt++)
#pragma unroll
        for (int nt = 0; nt < 4; nt++)
#pragma unroll
            for (int q = 0; q < 4; q++) c[mt][nt][q] = 0.0f;

    auto issue = [&](int kt, int buf) {
        uint32_t sA = sb + buf * STAGE_BYTES;
        uint32_t sB = sA + A_STAGE;
        int kc = kt * GBK;
#pragma unroll
        for (int q = 0; q < 4; q++) {
            int id = tid + q * 256;
            int m = id >> 3, ch = id & 7;
            int grow = row0 + m; if (grow >= GN) grow = 0;
            const char* src = Ab + (size_t)grow * 1536 + kc * 2 + ch * 16;
            CPA16(sA + sw128(m * 128 + ch * 16), src);
        }
#pragma unroll
        for (int q = 0; q < 2; q++) {
            int id = tid + q * 256;
            int n = id >> 3, ch = id & 7;
            const char* src = Bb + (size_t)(nb * 64 + n) * 1536 + kc * 2 + ch * 16;
            CPA16(sB + sw128(n * 128 + ch * 16), src);
        }
        CPA_COMMIT();
    };

    issue(0, 0);
    issue(1, 1);
    int cur = 0, ahead_buf = 2;
    for (int t = 0; t < KITERS; t++) {
        if (t + 2 < KITERS) {
            issue(t + 2, ahead_buf);
            ahead_buf = (ahead_buf == 2) ? 0 : ahead_buf + 1;
            asm volatile("cp.async.wait_group 2;");
        } else if (t + 1 < KITERS) {
            asm volatile("cp.async.wait_group 1;");
        } else {
            asm volatile("cp.async.wait_group 0;");
        }
        __syncthreads();
        uint32_t sA = sb + cur * STAGE_BYTES;
        uint32_t sB = sA + A_STAGE;
#pragma unroll
        for (int ks = 0; ks < 4; ks++) {
            int kb = ks * 16;
            uint32_t a[2][4], b[4][2];
#pragma unroll
            for (int mt = 0; mt < 2; mt++) {
                int m0 = warpM * 32 + mt * 16;
                uint32_t off = (uint32_t)(m0 + (lj & 1) * 8 + lr) * 128
                             + (uint32_t)(kb + (lj >> 1) * 8) * 2;
                ldsm_x4(a[mt][0], a[mt][1], a[mt][2], a[mt][3], sA + sw128(off));
            }
#pragma unroll
            for (int np = 0; np < 2; np++) {
                int ntj = np * 2 + (lj >> 1);
                uint32_t off = (uint32_t)(warpN * 32 + ntj * 8 + lr) * 128
                             + (uint32_t)(kb + (lj & 1) * 8) * 2;
                ldsm_x4(b[np * 2][0], b[np * 2][1], b[np * 2 + 1][0], b[np * 2 + 1][1],
                        sB + sw128(off));
            }
#pragma unroll
            for (int mt = 0; mt < 2; mt++)
#pragma unroll
                for (int nt = 0; nt < 4; nt++)
                    mma16816(c[mt][nt], a[mt], b[nt]);
        }
        __syncthreads();
        cur = (cur == 2) ? 0 : cur + 1;
    }

    float* C = (nb < 4) ? g_xl1 : g_xr1;
    int colBase = (nb & 3) * 64 + warpN * 32;
#pragma unroll
    for (int mt = 0; mt < 2; mt++) {
        int r0 = row0 + warpM * 32 + mt * 16 + g;
#pragma unroll
        for (int nt = 0; nt < 4; nt++) {
            int cc = colBase + nt * 8 + t2;
            if (r0 < GN)
                *reinterpret_cast<float2*>(C + (size_t)r0 * 256 + cc) =
                    make_float2(c[mt][nt][0], c[mt][nt][1]);
            if (r0 + 8 < GN)
                *reinterpret_cast<float2*>(C + (size_t)(r0 + 8) * 256 + cc) =
                    make_float2(c[mt][nt][2], c[mt][nt][3]);
        }
    }
}

// ---------------- layer1 fused: softmax-aggregate + bias/relu + (h @ W2) ----------------
__device__ __forceinline__ float score8(const float4& xl0, const float4& xl1,
                                        const float4& xr0, const float4& xr1,
                                        const float4& at0, const float4& at1) {
    float t = lrelu(xl0.x + xr0.x) * at0.x + lrelu(xl0.y + xr0.y) * at0.y
            + lrelu(xl0.z + xr0.z) * at0.z + lrelu(xl0.w + xr0.w) * at0.w
            + lrelu(xl1.x + xr1.x) * at1.x + lrelu(xl1.y + xr1.y) * at1.y
            + lrelu(xl1.z + xr1.z) * at1.z + lrelu(xl1.w + xr1.w) * at1.w;
    return t;
}

#define SOFTMAX_STEP(T, V0, V1) do { \
    float mn = fmaxf(m, (T)); \
    float f = __expf(m - mn); \
    float e = __expf((T) - mn); \
    d = d * f + e; \
    acc0.x = acc0.x * f + e * (V0).x; acc0.y = acc0.y * f + e * (V0).y; \
    acc0.z = acc0.z * f + e * (V0).z; acc0.w = acc0.w * f + e * (V0).w; \
    acc1.x = acc1.x * f + e * (V1).x; acc1.y = acc1.y * f + e * (V1).y; \
    acc1.z = acc1.z * f + e * (V1).z; acc1.w = acc1.w * f + e * (V1).w; \
    m = mn; \
} while (0)

__global__ void layer1_fused_kernel(const float* __restrict__ att1,
                                    const float* __restrict__ b1,
                                    const float* __restrict__ Wl2,
                                    const float* __restrict__ Wr2) {
    // sW[q][lane][jj] (jj padded to 21): W2cat[lane*8+q][jj], conflict-free reads
    __shared__ float sW[8 * 32 * 21];
    int tid = threadIdx.x;
    for (int i = tid; i < 8 * 32 * 20; i += 256) {
        int jj = i % 20;
        int cidx = i / 20;            // 0..255 channel
        int q = cidx & 7, ls = cidx >> 3;
        float w = (jj < 10) ? Wl2[cidx * 10 + jj] : Wr2[cidx * 10 + (jj - 10)];
        sW[q * (32 * 21) + ls * 21 + jj] = w;
    }
    __syncthreads();

    int gt = blockIdx.x * blockDim.x + tid;
    int node = gt >> 5;
    int lane = tid & 31;
    if (node >= GN) return;

    const float4* xr4 = reinterpret_cast<const float4*>(g_xr1) + (size_t)node * 64;
    float4 xr0 = xr4[lane * 2];
    float4 xr1 = xr4[lane * 2 + 1];
    float4 at0 = reinterpret_cast<const float4*>(att1)[lane * 2];
    float4 at1 = reinterpret_cast<const float4*>(att1)[lane * 2 + 1];

    float4 acc0 = make_float4(0.f, 0.f, 0.f, 0.f);
    float4 acc1 = make_float4(0.f, 0.f, 0.f, 0.f);
    float m = -CUDART_INF_F, d = 0.0f;

    int beg = g_rowptr[node], end = g_rowptr[node + 1];
    int j = beg;
    for (; j + 2 <= end; j += 2) {
        int s0 = g_csr_src[j];
        int s1 = g_csr_src[j + 1];
        const float4* p0 = reinterpret_cast<const float4*>(g_xl1) + (size_t)s0 * 64 + lane * 2;
        const float4* p1 = reinterpret_cast<const float4*>(g_xl1) + (size_t)s1 * 64 + lane * 2;
        float4 a0 = __ldg(p0);
        float4 a1 = __ldg(p0 + 1);
        float4 c0 = __ldg(p1);
        float4 c1 = __ldg(p1 + 1);

        float t0 = score8(a0, a1, xr0, xr1, at0, at1);
        float t1 = score8(c0, c1, xr0, xr1, at0, at1);
        t0 += __shfl_xor_sync(0xffffffffu, t0, 4);
        t1 += __shfl_xor_sync(0xffffffffu, t1, 4);
        t0 += __shfl_xor_sync(0xffffffffu, t0, 2);
        t1 += __shfl_xor_sync(0xffffffffu, t1, 2);
        t0 += __shfl_xor_sync(0xffffffffu, t0, 1);
        t1 += __shfl_xor_sync(0xffffffffu, t1, 1);

        SOFTMAX_STEP(t0, a0, a1);
        SOFTMAX_STEP(t1, c0, c1);
    }
    if (j < end) {
        int s0 = g_csr_src[j];
        const float4* p0 = reinterpret_cast<const float4*>(g_xl1) + (size_t)s0 * 64 + lane * 2;
        float4 a0 = __ldg(p0);
        float4 a1 = __ldg(p0 + 1);
        float t0 = score8(a0, a1, xr0, xr1, at0, at1);
        t0 += __shfl_xor_sync(0xffffffffu, t0, 4);
        t0 += __shfl_xor_sync(0xffffffffu, t0, 2);
        t0 += __shfl_xor_sync(0xffffffffu, t0, 1);
        SOFTMAX_STEP(t0, a0, a1);
    }

    float inv = 1.0f / d;
    float4 bb0 = reinterpret_cast<const float4*>(b1)[lane * 2];
    float4 bb1 = reinterpret_cast<const float4*>(b1)[lane * 2 + 1];
    float hv[8];
    hv[0] = fmaxf(acc0.x * inv + bb0.x, 0.f); hv[1] = fmaxf(acc0.y * inv + bb0.y, 0.f);
    hv[2] = fmaxf(acc0.z * inv + bb0.z, 0.f); hv[3] = fmaxf(acc0.w * inv + bb0.w, 0.f);
    hv[4] = fmaxf(acc1.x * inv + bb1.x, 0.f); hv[5] = fmaxf(acc1.y * inv + bb1.y, 0.f);
    hv[6] = fmaxf(acc1.z * inv + bb1.z, 0.f); hv[7] = fmaxf(acc1.w * inv + bb1.w, 0.f);

    // fused h @ [Wl2 | Wr2]: 20 outputs per node
    const float* sWl = &sW[lane * 21];
    float myval = 0.0f;
#pragma unroll
    for (int jj = 0; jj < 20; jj++) {
        float s = 0.0f;
#pragma unroll
        for (int q = 0; q < 8; q++)
            s += hv[q] * sWl[q * (32 * 21) + jj];
        s += __shfl_xor_sync(0xffffffffu, s, 16);
        s += __shfl_xor_sync(0xffffffffu, s, 8);
        s += __shfl_xor_sync(0xffffffffu, s, 4);
        s += __shfl_xor_sync(0xffffffffu, s, 2);
        s += __shfl_xor_sync(0xffffffffu, s, 1);
        if (lane == jj) myval = s;
    }
    if (lane < 10)       g_hl2[node * 10 + lane] = myval;
    else if (lane < 20)  g_hr2[node * 10 + lane - 10] = myval;
}

// ---------------- layer2 fused: two 16-lane halves with per-half shfl masks ----------------
__global__ void layer2_fused_kernel(const float* __restrict__ att2,
                                    const float* __restrict__ b2,
                                    float* __restrict__ out) {
    int gt = blockIdx.x * blockDim.x + threadIdx.x;
    int node = gt >> 5;
    int lane = threadIdx.x & 31;
    if (node >= GN) return;

    int half = lane >> 4;        // 0 or 1
    int hl_lane = lane & 15;     // channel within half (0..9 active)
    unsigned hm = half ? 0xffff0000u : 0x0000ffffu;   // per-half mask (trip counts differ!)
    float hr = (hl_lane < 10) ? g_hr2[node * 10 + hl_lane] : 0.0f;
    float at = (hl_lane < 10) ? att2[hl_lane] : 0.0f;
    float m = -CUDART_INF_F, d = 0.0f, acc = 0.0f;

    int beg = g_rowptr[node], end = g_rowptr[node + 1];
    // half h processes edges beg+h, beg+h+2, ... (independent online softmax per half)
    for (int j = beg + half; j < end; j += 2) {
        int src = g_csr_src[j];
        float hl = (hl_lane < 10) ? __ldg(&g_hl2[src * 10 + hl_lane]) : 0.0f;
        float v = lrelu(hl + hr) * at;
        v += __shfl_xor_sync(hm, v, 8);
        v += __shfl_xor_sync(hm, v, 4);
        v += __shfl_xor_sync(hm, v, 2);
        v += __shfl_xor_sync(hm, v, 1);
        float s = v;   // sum within this 16-lane half
        float mn = fmaxf(m, s);
        float f = __expf(m - mn);
        float e = __expf(s - mn);
        d = d * f + e;
        acc = acc * f + e * hl;
        m = mn;
    }

    // merge the two halves' softmax states (lane i <-> lane i^16); fully converged here
    float m2 = __shfl_xor_sync(0xffffffffu, m, 16);
    float d2 = __shfl_xor_sync(0xffffffffu, d, 16);
    float a2 = __shfl_xor_sync(0xffffffffu, acc, 16);
    float mn = fmaxf(m, m2);
    float f1 = (m == -CUDART_INF_F) ? 0.0f : __expf(m - mn);
    float f2 = (m2 == -CUDART_INF_F) ? 0.0f : __expf(m2 - mn);
    d = d * f1 + d2 * f2;
    acc = acc * f1 + a2 * f2;

    if (lane < 10)
        out[node * 10 + lane] = acc / d + b2[lane];
}

// ---------------- launch ----------------
extern "C" void kernel_launch(void* const* d_in, const int* in_sizes, int n_in,
                              void* d_out, int out_size) {
    const float* x    = (const float*)d_in[0];
    const int*   ei   = (const int*)d_in[1];
    const float* Wl1  = (const float*)d_in[2];
    const float* Wr1  = (const float*)d_in[3];
    const float* att1 = (const float*)d_in[4];
    const float* b1   = (const float*)d_in[5];
    const float* Wl2  = (const float*)d_in[6];
    const float* Wr2  = (const float*)d_in[7];
    const float* att2 = (const float*)d_in[8];
    const float* b2   = (const float*)d_in[9];
    float* out = (float*)d_out;

    static cudaStream_t s2 = nullptr;
    static cudaEvent_t ev_fork = nullptr, ev_join = nullptr;
    static int inited = 0;
    if (!inited) {
        cudaFuncSetAttribute(gemm1_mma_kernel,
                             cudaFuncAttributeMaxDynamicSharedMemorySize, GSMEM_BYTES);
        cudaStreamCreateWithFlags(&s2, cudaStreamNonBlocking);
        cudaEventCreateWithFlags(&ev_fork, cudaEventDisableTiming);
        cudaEventCreateWithFlags(&ev_join, cudaEventDisableTiming);
        inited = 1;
    }

    // fork: CSR build chain on s2, converts + gemm1 on the main stream.
    // Submission order keeps gemm1 at slot #4 (the profiled slot).
    cudaEventRecord(ev_fork, 0);
    cudaStreamWaitEvent(s2, ev_fork, 0);

    convert_x_kernel<<<(GN * 64 + 255) / 256, 256>>>(x);                 // 1 (main)
    convert_w_kernel<<<(512 * 256 + 255) / 256, 256>>>(Wl1, Wr1);        // 2 (main)
    zero_cnt_kernel<<<(GN + 255) / 256, 256, 0, s2>>>();                 // 3 (s2)

    dim3 g1(8, (GN + GBM - 1) / GBM);                                    // nb fastest
    gemm1_mma_kernel<<<g1, 256, GSMEM_BYTES>>>();                        // 4 (main) <-- profiled

    hist_kernel<<<(GET + 255) / 256, 256, 0, s2>>>(ei);                  // s2
    scan1_kernel<<<NSCAN_BLK, 1024, 0, s2>>>();                          // s2
    scan2_kernel<<<1, 64, 0, s2>>>();                                    // s2
    scan3_kernel<<<NSCAN_BLK, 1024, 0, s2>>>();                          // s2
    scatter_kernel<<<(GET + 255) / 256, 256, 0, s2>>>(ei);               // s2
    cudaEventRecord(ev_join, s2);

    // join: layer1 needs both gemm1 (main) and CSR (s2)
    cudaStreamWaitEvent(0, ev_join, 0);

    layer1_fused_kernel<<<(GN * 32 + 255) / 256, 256>>>(att1, b1, Wl2, Wr2);
    layer2_fused_kernel<<<(GN * 32 + 255) / 256, 256>>>(att2, b2, out);
}